// round 12
// baseline (speedup 1.0000x reference)
#include <cuda_runtime.h>
#include <cuda_fp16.h>
#include <stdint.h>
#include <math.h>

#define FULL 0xffffffffu

static const int NB    = 16;
static const int NN    = 1024;
static const int NNODE = NB * NN;   // 16384
static const int MAXN  = 192;

// -------- static device scratch (no allocations allowed) --------
__device__ float g_u[2][NNODE * 8 + 8];
__device__ float g_s[NNODE * 12];
__device__ float g_yhp[8 * NNODE];
__device__ float g_hhp[8 * NNODE];
__device__ float g_deg[NNODE];
__device__ float g_eg[NNODE];
__device__ int   g_nbru[NNODE * MAXN];
__device__ int   g_cnt[NNODE];
__device__ __half g_Hhi[(size_t)NB * NN * NN];
__device__ __half g_Hlo[(size_t)NB * NN * NN];
__device__ __half g_adjh[(size_t)NB * NN * NN];

__device__ __forceinline__ uint32_t sm_u32(const void* p) {
    uint32_t a;
    asm("{ .reg .u64 t; cvta.to.shared.u64 t, %1; cvt.u32.u64 %0, t; }"
        : "=r"(a) : "l"(p));
    return a;
}
__device__ __forceinline__ void cpasync16(uint32_t dst, const void* src) {
    asm volatile("cp.async.cg.shared.global [%0], [%1], 16;"
                 :: "r"(dst), "l"(src) : "memory");
}
__device__ __forceinline__ void ldsm4(uint32_t& r0, uint32_t& r1, uint32_t& r2,
                                      uint32_t& r3, uint32_t a) {
    asm volatile("ldmatrix.sync.aligned.m8n8.x4.shared.b16 {%0,%1,%2,%3}, [%4];"
                 : "=r"(r0), "=r"(r1), "=r"(r2), "=r"(r3) : "r"(a));
}
__device__ __forceinline__ void mma16816(float* c, uint32_t a0, uint32_t a1,
                                         uint32_t a2, uint32_t a3,
                                         uint32_t b0, uint32_t b1) {
    asm volatile(
        "mma.sync.aligned.m16n8k16.row.col.f32.f16.f16.f32 "
        "{%0,%1,%2,%3}, {%4,%5,%6,%7}, {%8,%9}, {%0,%1,%2,%3};"
        : "+f"(c[0]), "+f"(c[1]), "+f"(c[2]), "+f"(c[3])
        : "r"(a0), "r"(a1), "r"(a2), "r"(a3), "r"(b0), "r"(b1));
}

// fast activations (HW EX2/RCP paths, clamped against overflow)
__device__ __forceinline__ float sigf(float x) {
    float e = __expf(-fmaxf(x, -80.f));
    return __fdividef(1.f, 1.f + e);
}
__device__ __forceinline__ float tanhff(float x) {
    float xc = fminf(fmaxf(x, -15.f), 15.f);
    float t  = __expf(2.f * xc);
    return __fdividef(t - 1.f, t + 1.f);
}

// -------- one pass over H: yh/hh partials + fp16 hi/lo split --------
__global__ void k_convcol(const float* __restrict__ H, const float* __restrict__ y) {
    __shared__ float sy[128];
    int b = blockIdx.x, j = blockIdx.y * 128 + threadIdx.x, k0 = blockIdx.z * 128;
    sy[threadIdx.x] = y[b * NN + k0 + threadIdx.x];
    __syncthreads();
    const float* Hb = H + ((size_t)b * NN + k0) * NN + j;
    __half* hi = g_Hhi + ((size_t)b * NN + k0) * NN + j;
    __half* lo = g_Hlo + ((size_t)b * NN + k0) * NN + j;
    float yh = 0.f, hh = 0.f;
#pragma unroll 4
    for (int i = 0; i < 128; ++i) {
        float h = Hb[(size_t)i * NN];
        __half hb = __float2half(h);
        hi[(size_t)i * NN] = hb;
        lo[(size_t)i * NN] = __float2half(h - __half2float(hb));
        yh += sy[i] * h;
        hh += h * h;
    }
    int node = b * NN + j;
    g_yhp[blockIdx.z * NNODE + node] = yh;
    g_hhp[blockIdx.z * NNODE + node] = hh;
}

// -------- adj pass: neighbor lists + deg + fp16 adj + zero-init --------
__global__ void k_csr(const float* __restrict__ adj) {
    int row  = blockIdx.x * (blockDim.x >> 5) + (threadIdx.x >> 5);
    int lane = threadIdx.x & 31;
    const float* ar = adj + (size_t)row * NN;
    __half* ah = g_adjh + (size_t)row * NN;
    const __half ONE = __float2half(1.f), ZERO = __float2half(0.f);
    int base = row * MAXN;
    int boff = (row >> 10) << 10;
    int cnt  = 0;
    for (int c = 0; c < NN; c += 32) {
        float a = ar[c + lane];
        ah[c + lane] = (a != 0.f) ? ONE : ZERO;
        unsigned m = __ballot_sync(FULL, a != 0.f);
        if (a != 0.f) {
            int pos = cnt + __popc(m & ((1u << lane) - 1u));
            if (pos < MAXN) g_nbru[base + pos] = (boff + c + lane) * 8;
        }
        cnt += __popc(m);
    }
    int cntc = cnt < MAXN ? cnt : MAXN;
    int cntp = (cntc + 7) & ~7;   // pad to x8 for 8-lane gather
    if (lane < cntp - cntc) g_nbru[base + cntc + lane] = NNODE * 8;  // zero u row
    if (lane == 0) {
        g_cnt[row] = cntc;
        g_deg[row] = (float)cnt;
        g_eg[row]  = 0.f;
    }
    if (lane < 12) g_s[(size_t)row * 12 + lane] = 0.f;
    if (row == 0 && lane < 8) { g_u[0][NNODE * 8 + lane] = 0.f; g_u[1][NNODE * 8 + lane] = 0.f; }
}

// -------- eg via mma.sync: T = (Hhi+Hlo) @ adj^T, eg_i = sum_k H[k,i]*T[k,i] --
static const int TSTRIDE = 80;              // bytes per tile row (40 halves)
static const int TILEB   = 128 * TSTRIDE;   // 10240 B per tile
static const int STAGEB  = 3 * TILEB;       // Ahi, Alo, B per stage

__global__ void __launch_bounds__(256, 2) k_gemm(const float* __restrict__ H,
                                                 const float* __restrict__ W1w,
                                                 const float* __restrict__ W1b,
                                                 const float* __restrict__ b1) {
    extern __shared__ __align__(16) char smb[];
    const int tid = threadIdx.x, wid = tid >> 5, lane = tid & 31;
    const int g = lane >> 2, t = lane & 3;
    const int b = blockIdx.z;
    const int i0 = blockIdx.x * 128, k0 = blockIdx.y * 128;
    const int wm = wid & 1, wn = wid >> 1;

    // u0 = W1([yh,hh]) finalize on the 128 blocks with blockIdx.y==0
    if (blockIdx.y == 0 && tid < 128) {
        int node = (b * 8 + blockIdx.x) * 128 + tid;
        float yh = 0.f, hh = 0.f;
#pragma unroll
        for (int z = 0; z < 8; ++z) {
            yh += g_yhp[z * NNODE + node];
            hh += g_hhp[z * NNODE + node];
        }
        float* up = &g_u[0][(size_t)node * 8];
#pragma unroll
        for (int c = 0; c < 8; ++c)
            up[c] = W1w[2 * c] * yh + W1w[2 * c + 1] * hh + W1b[c] + b1[c];
    }

    const __half* Ahi = g_Hhi  + ((size_t)b * NN + k0) * NN;
    const __half* Alo = g_Hlo  + ((size_t)b * NN + k0) * NN;
    const __half* Bad = g_adjh + ((size_t)b * NN + i0) * NN;
    const uint32_t sbase = sm_u32(smb);

    const int arow = (lane & 7) + ((lane >> 3) & 1) * 8;
    const int acol = (lane >> 4) * 16;
    const int brow = (lane & 7) + (lane >> 4) * 8;
    const int bcol = ((lane >> 3) & 1) * 16;

    float acc[4][4][4];
#pragma unroll
    for (int a = 0; a < 4; ++a)
#pragma unroll
        for (int n = 0; n < 4; ++n)
#pragma unroll
            for (int r = 0; r < 4; ++r) acc[a][n][r] = 0.f;

    auto issue = [&](int c) {
        int j0 = c * 32;
        uint32_t tb = sbase + (c % 3) * STAGEB;
#pragma unroll
        for (int q = 0; q < 2; ++q) {
            int idx = tid + q * 256;
            int row = idx >> 2, quad = idx & 3;
            uint32_t so = tb + row * TSTRIDE + quad * 16;
            cpasync16(so,             Ahi + (size_t)row * NN + j0 + quad * 8);
            cpasync16(so + TILEB,     Alo + (size_t)row * NN + j0 + quad * 8);
            cpasync16(so + 2 * TILEB, Bad + (size_t)row * NN + j0 + quad * 8);
        }
        asm volatile("cp.async.commit_group;" ::: "memory");
    };

    issue(0);
    issue(1);
    for (int c = 0; c < 32; ++c) {
        if (c < 31) asm volatile("cp.async.wait_group 1;" ::: "memory");
        else        asm volatile("cp.async.wait_group 0;" ::: "memory");
        __syncthreads();
        if (c < 30) issue(c + 2);
        uint32_t sA = sbase + (c % 3) * STAGEB;
        uint32_t sL = sA + TILEB, sB = sA + 2 * TILEB;
#pragma unroll
        for (int ks = 0; ks < 2; ++ks) {
            uint32_t bfr[4][2];
            ldsm4(bfr[0][0], bfr[0][1], bfr[1][0], bfr[1][1],
                  sB + (wn * 32 + brow) * TSTRIDE + ks * 32 + bcol);
            ldsm4(bfr[2][0], bfr[2][1], bfr[3][0], bfr[3][1],
                  sB + (wn * 32 + 16 + brow) * TSTRIDE + ks * 32 + bcol);
#pragma unroll
            for (int sp = 0; sp < 2; ++sp) {
                uint32_t sa = sp ? sL : sA;
#pragma unroll
                for (int mi = 0; mi < 4; ++mi) {
                    uint32_t a0, a1, a2, a3;
                    ldsm4(a0, a1, a2, a3,
                          sa + (wm * 64 + mi * 16 + arow) * TSTRIDE + ks * 32 + acol);
#pragma unroll
                    for (int ni = 0; ni < 4; ++ni)
                        mma16816(acc[mi][ni], a0, a1, a2, a3, bfr[ni][0], bfr[ni][1]);
                }
            }
        }
    }

    const float* Hb = H + ((size_t)b * NN + k0) * NN + i0;
#pragma unroll
    for (int ni = 0; ni < 4; ++ni) {
        int col = wn * 32 + ni * 8 + 2 * t;
        float p0 = 0.f, p1 = 0.f;
#pragma unroll
        for (int mi = 0; mi < 4; ++mi) {
            int m = wm * 64 + mi * 16;
            float2 h0 = *(const float2*)(Hb + (size_t)(m + g) * NN + col);
            float2 h1 = *(const float2*)(Hb + (size_t)(m + g + 8) * NN + col);
            p0 += acc[mi][ni][0] * h0.x + acc[mi][ni][2] * h1.x;
            p1 += acc[mi][ni][1] * h0.y + acc[mi][ni][3] * h1.y;
        }
#pragma unroll
        for (int o = 4; o < 32; o <<= 1) {
            p0 += __shfl_xor_sync(FULL, p0, o);
            p1 += __shfl_xor_sync(FULL, p1, o);
        }
        if (g == 0) {
            atomicAdd(&g_eg[b * NN + i0 + col], p0);
            atomicAdd(&g_eg[b * NN + i0 + col + 1], p1);
        }
    }
}

// -------- fused per-node: 2-phase (256-thread gather, warp-0 compute) ------
// Phase 1: 8 lanes/node gather ns for 32 nodes -> smem. Phase 2: warp 0
// computes 32 nodes with all lanes active (MLP+GRU+W2, readout on last).
__global__ void k_node(const float* __restrict__ r, const float* __restrict__ nur,
                       const float* __restrict__ Wm1, const float* __restrict__ Wm1b,
                       const float* __restrict__ Wm2, const float* __restrict__ Wm2b,
                       const float* __restrict__ wih, const float* __restrict__ whh,
                       const float* __restrict__ bih, const float* __restrict__ bhh,
                       const float* __restrict__ W2,  const float* __restrict__ W2b,
                       const float* __restrict__ b2,
                       const float* __restrict__ Wr1, const float* __restrict__ Wr1b,
                       const float* __restrict__ Wr2, const float* __restrict__ Wr2b,
                       int bufin, int last, float* __restrict__ out) {
    __shared__ float w[1690];
    __shared__ float sns[32][9];
    {
        int t = threadIdx.x;
        for (int i = t; i < 384; i += blockDim.x) w[i]        = Wm1[i];
        for (int i = t; i < 16;  i += blockDim.x) w[384 + i]  = Wm1b[i];
        for (int i = t; i < 128; i += blockDim.x) w[400 + i]  = Wm2[i];
        for (int i = t; i < 8;   i += blockDim.x) w[528 + i]  = Wm2b[i];
        for (int i = t; i < 360; i += blockDim.x) w[536 + i]  = wih[i];
        for (int i = t; i < 432; i += blockDim.x) w[896 + i]  = whh[i];
        for (int i = t; i < 36;  i += blockDim.x) w[1328 + i] = bih[i];
        for (int i = t; i < 36;  i += blockDim.x) w[1364 + i] = bhh[i];
        for (int i = t; i < 96;  i += blockDim.x) w[1400 + i] = W2[i];
        for (int i = t; i < 8;   i += blockDim.x) w[1496 + i] = W2b[i] + b2[i];
        for (int i = t; i < 128; i += blockDim.x) w[1512 + i] = Wr1[i];
        for (int i = t; i < 16;  i += blockDim.x) w[1640 + i] = Wr1b[i];
        for (int i = t; i < 32;  i += blockDim.x) w[1656 + i] = Wr2[i];
        for (int i = t; i < 2;   i += blockDim.x) w[1688 + i] = Wr2b[i];
    }
    __syncthreads();
    const float* uin = g_u[bufin];
    float* uout = g_u[bufin ^ 1];

    // ---- phase 1: gather (8 lanes per node, 32 nodes per block) ----
    {
        int q    = threadIdx.x & 7;
        int nib  = threadIdx.x >> 3;
        int node = blockIdx.x * 32 + nib;
        float ns[8] = {0, 0, 0, 0, 0, 0, 0, 0};
        int nq = ((g_cnt[node] + 7) & ~7) >> 2;   // quads, padded to x8 nbrs
        const int4* off = (const int4*)&g_nbru[node * MAXN];
        for (int i = q; i < nq; i += 8) {
            int4 o = off[i];
            const float4* p0 = (const float4*)(uin + o.x);
            const float4* p1 = (const float4*)(uin + o.y);
            const float4* p2 = (const float4*)(uin + o.z);
            const float4* p3 = (const float4*)(uin + o.w);
            float4 a0 = p0[0], b0 = p0[1];
            float4 a1 = p1[0], b1 = p1[1];
            float4 a2 = p2[0], b2v = p2[1];
            float4 a3 = p3[0], b3 = p3[1];
            ns[0] += a0.x + a1.x + a2.x + a3.x;
            ns[1] += a0.y + a1.y + a2.y + a3.y;
            ns[2] += a0.z + a1.z + a2.z + a3.z;
            ns[3] += a0.w + a1.w + a2.w + a3.w;
            ns[4] += b0.x + b1.x + b2v.x + b3.x;
            ns[5] += b0.y + b1.y + b2v.y + b3.y;
            ns[6] += b0.z + b1.z + b2v.z + b3.z;
            ns[7] += b0.w + b1.w + b2v.w + b3.w;
        }
#pragma unroll
        for (int c = 0; c < 8; ++c) {
            ns[c] += __shfl_xor_sync(FULL, ns[c], 1);
            ns[c] += __shfl_xor_sync(FULL, ns[c], 2);
            ns[c] += __shfl_xor_sync(FULL, ns[c], 4);
        }
        if (q == 0) {
#pragma unroll
            for (int c = 0; c < 8; ++c) sns[nib][c] = ns[c];
        }
    }
    __syncthreads();
    if (threadIdx.x >= 32) return;

    // ---- phase 2: warp 0, one node per lane, all lanes active ----
    int lane = threadIdx.x;
    int node = blockIdx.x * 32 + lane;

    float ns[8];
#pragma unroll
    for (int c = 0; c < 8; ++c) ns[c] = sns[lane][c];

    float rv  = r[node];
    float nuv = fmaxf(nur[node], 1e-10f);
    float deg = g_deg[node], eg = g_eg[node];

    float u[8];
    {
        const float4* up = (const float4*)(uin + (size_t)node * 8);
        float4 a = up[0], b4 = up[1];
        u[0] = a.x; u[1] = a.y; u[2] = a.z; u[3] = a.w;
        u[4] = b4.x; u[5] = b4.y; u[6] = b4.z; u[7] = b4.w;
    }

    float m[8];
    {
        float hid[16];
#pragma unroll
        for (int t = 0; t < 16; ++t) {
            float h = w[384 + t];
#pragma unroll
            for (int c = 0; c < 8; ++c) h += w[t * 24 + c] * (u[c] * deg);
#pragma unroll
            for (int c = 0; c < 8; ++c) h += w[t * 24 + 8 + c] * ns[c];
#pragma unroll
            for (int c = 0; c < 8; ++c) h += w[t * 24 + 16 + c] * eg;
            hid[t] = fmaxf(h, 0.f);
        }
#pragma unroll
        for (int o = 0; o < 8; ++o) {
            float v = w[528 + o];
#pragma unroll
            for (int t = 0; t < 16; ++t) v += w[400 + o * 16 + t] * hid[t];
            m[o] = v;
        }
    }

    float x[10];
#pragma unroll
    for (int c = 0; c < 8; ++c) x[c] = m[c];
    x[8] = rv;
    x[9] = nuv;

    float s[12];
#pragma unroll
    for (int c = 0; c < 12; ++c) s[c] = g_s[(size_t)node * 12 + c];

    float sn[12];
#pragma unroll
    for (int g = 0; g < 12; ++g) {
        float xr = w[1328 + g], xz = w[1328 + 12 + g], xn = w[1328 + 24 + g];
#pragma unroll
        for (int c = 0; c < 10; ++c) {
            float xv = x[c];
            xr += w[536 + g * 10 + c] * xv;
            xz += w[536 + (12 + g) * 10 + c] * xv;
            xn += w[536 + (24 + g) * 10 + c] * xv;
        }
        float hr = w[1364 + g], hz = w[1364 + 12 + g], hn = w[1364 + 24 + g];
#pragma unroll
        for (int c = 0; c < 12; ++c) {
            float sv = s[c];
            hr += w[896 + g * 12 + c] * sv;
            hz += w[896 + (12 + g) * 12 + c] * sv;
            hn += w[896 + (24 + g) * 12 + c] * sv;
        }
        float rg = sigf(xr + hr);
        float zg = sigf(xz + hz);
        float ng = tanhff(xn + rg * hn);
        sn[g] = (1.f - zg) * ng + zg * s[g];
    }
#pragma unroll
    for (int c = 0; c < 12; ++c) g_s[(size_t)node * 12 + c] = sn[c];

    float un[8];
#pragma unroll
    for (int o = 0; o < 8; ++o) {
        float v = w[1496 + o];
#pragma unroll
        for (int c = 0; c < 12; ++c) v += w[1400 + o * 12 + c] * sn[c];
        un[o] = v;
    }
    {
        float4* op = (float4*)(uout + (size_t)node * 8);
        op[0] = make_float4(un[0], un[1], un[2], un[3]);
        op[1] = make_float4(un[4], un[5], un[6], un[7]);
    }

    if (last) {
        float hid[16];
#pragma unroll
        for (int t = 0; t < 16; ++t) {
            float h = w[1640 + t];
#pragma unroll
            for (int c = 0; c < 8; ++c) h += w[1512 + t * 8 + c] * un[c];
            hid[t] = fmaxf(h, 0.f);
        }
        float l0 = w[1688], l1 = w[1689];
#pragma unroll
        for (int t = 0; t < 16; ++t) {
            l0 += w[1656 + t] * hid[t];
            l1 += w[1656 + 16 + t] * hid[t];
        }
        float mx = fmaxf(l0, l1);
        float e0 = __expf(l0 - mx), e1 = __expf(l1 - mx);
        float inv = __fdividef(1.f, e0 + e1);
        float p0 = e0 * inv, p1 = e1 * inv;
        const float q0 = -0.70710678118654752440f, q1 = 0.70710678118654752440f;
        float xh = p0 * q0 + p1 * q1;
        float nu = p0 * (q0 - xh) * (q0 - xh) + p1 * (q1 - xh) * (q1 - xh);
        nu = fmaxf(nu, 1e-10f);
        out[node]         = xh;
        out[NNODE + node] = nu;
    }
}

extern "C" void kernel_launch(void* const* d_in, const int* in_sizes, int n_in,
                              void* d_out, int out_size) {
    const float* y    = (const float*)d_in[0];
    const float* H    = (const float*)d_in[1];
    const float* r    = (const float*)d_in[2];
    const float* nur  = (const float*)d_in[3];
    const float* adj  = (const float*)d_in[4];
    const float* W1w  = (const float*)d_in[5];
    const float* W1b  = (const float*)d_in[6];
    const float* b1   = (const float*)d_in[7];
    const float* Wm1  = (const float*)d_in[8];
    const float* Wm1b = (const float*)d_in[9];
    const float* Wm2  = (const float*)d_in[10];
    const float* Wm2b = (const float*)d_in[11];
    const float* wih  = (const float*)d_in[12];
    const float* whh  = (const float*)d_in[13];
    const float* bih  = (const float*)d_in[14];
    const float* bhh  = (const float*)d_in[15];
    const float* W2   = (const float*)d_in[16];
    const float* W2b  = (const float*)d_in[17];
    const float* b2   = (const float*)d_in[18];
    const float* Wr1  = (const float*)d_in[19];
    const float* Wr1b = (const float*)d_in[20];
    const float* Wr2  = (const float*)d_in[21];
    const float* Wr2b = (const float*)d_in[22];
    float* out = (float*)d_out;

    const int GEMM_SMEM = 3 * STAGEB;   // 92160 B
    cudaFuncSetAttribute(k_gemm, cudaFuncAttributeMaxDynamicSharedMemorySize, GEMM_SMEM);

    // fork: k_convcol (H pass) on side stream, k_csr (adj pass) on main stream
    cudaStream_t s2;
    cudaStreamCreateWithFlags(&s2, cudaStreamNonBlocking);
    cudaEvent_t evF, evJ;
    cudaEventCreateWithFlags(&evF, cudaEventDisableTiming);
    cudaEventCreateWithFlags(&evJ, cudaEventDisableTiming);
    cudaEventRecord(evF, 0);
    cudaStreamWaitEvent(s2, evF, 0);
    k_convcol<<<dim3(NB, NN / 128, 8), 128, 0, s2>>>(H, y);
    k_csr<<<NNODE / 8, 256>>>(adj);
    cudaEventRecord(evJ, s2);
    cudaStreamWaitEvent(0, evJ, 0);

    k_gemm<<<dim3(8, 8, NB), 256, GEMM_SMEM>>>(H, W1w, W1b, b1);
    k_node<<<NNODE / 32, 256>>>(r, nur, Wm1, Wm1b, Wm2, Wm2b, wih, whh, bih, bhh,
                                W2, W2b, b2, Wr1, Wr1b, Wr2, Wr2b, 0, 0, out);
    k_node<<<NNODE / 32, 256>>>(r, nur, Wm1, Wm1b, Wm2, Wm2b, wih, whh, bih, bhh,
                                W2, W2b, b2, Wr1, Wr1b, Wr2, Wr2b, 1, 1, out);

    cudaEventDestroy(evF);
    cudaEventDestroy(evJ);
    cudaStreamDestroy(s2);
}

// round 13
// speedup vs baseline: 1.0939x; 1.0939x over previous
#include <cuda_runtime.h>
#include <cuda_fp16.h>
#include <stdint.h>
#include <math.h>

#define FULL 0xffffffffu

static const int NB    = 16;
static const int NN    = 1024;
static const int NNODE = NB * NN;   // 16384
static const int MAXN  = 192;

// -------- static device scratch (no allocations allowed) --------
__device__ float g_u[2][NNODE * 8 + 8];
__device__ float g_s[NNODE * 12];
__device__ float g_yhp[8 * NNODE];
__device__ float g_hhp[8 * NNODE];
__device__ float g_deg[NNODE];
__device__ float g_eg[NNODE];
__device__ int   g_nbru[NNODE * MAXN];
__device__ int   g_cnt[NNODE];
__device__ __half g_Hhi[(size_t)NB * NN * NN];
__device__ __half g_Hlo[(size_t)NB * NN * NN];
__device__ __half g_adjh[(size_t)NB * NN * NN];

__device__ __forceinline__ uint32_t sm_u32(const void* p) {
    uint32_t a;
    asm("{ .reg .u64 t; cvta.to.shared.u64 t, %1; cvt.u32.u64 %0, t; }"
        : "=r"(a) : "l"(p));
    return a;
}
__device__ __forceinline__ void cpasync16(uint32_t dst, const void* src) {
    asm volatile("cp.async.cg.shared.global [%0], [%1], 16;"
                 :: "r"(dst), "l"(src) : "memory");
}
__device__ __forceinline__ void ldsm4(uint32_t& r0, uint32_t& r1, uint32_t& r2,
                                      uint32_t& r3, uint32_t a) {
    asm volatile("ldmatrix.sync.aligned.m8n8.x4.shared.b16 {%0,%1,%2,%3}, [%4];"
                 : "=r"(r0), "=r"(r1), "=r"(r2), "=r"(r3) : "r"(a));
}
__device__ __forceinline__ void mma16816(float* c, uint32_t a0, uint32_t a1,
                                         uint32_t a2, uint32_t a3,
                                         uint32_t b0, uint32_t b1) {
    asm volatile(
        "mma.sync.aligned.m16n8k16.row.col.f32.f16.f16.f32 "
        "{%0,%1,%2,%3}, {%4,%5,%6,%7}, {%8,%9}, {%0,%1,%2,%3};"
        : "+f"(c[0]), "+f"(c[1]), "+f"(c[2]), "+f"(c[3])
        : "r"(a0), "r"(a1), "r"(a2), "r"(a3), "r"(b0), "r"(b1));
}

// fast activations (HW EX2/RCP paths, clamped against overflow)
__device__ __forceinline__ float sigf(float x) {
    float e = __expf(-fmaxf(x, -80.f));
    return __fdividef(1.f, 1.f + e);
}
__device__ __forceinline__ float tanhff(float x) {
    float xc = fminf(fmaxf(x, -15.f), 15.f);
    float t  = __expf(2.f * xc);
    return __fdividef(t - 1.f, t + 1.f);
}

// -------- one pass over H: yh/hh partials + fp16 hi/lo split --------
__global__ void k_convcol(const float* __restrict__ H, const float* __restrict__ y) {
    __shared__ float sy[128];
    int b = blockIdx.x, j = blockIdx.y * 128 + threadIdx.x, k0 = blockIdx.z * 128;
    sy[threadIdx.x] = y[b * NN + k0 + threadIdx.x];
    __syncthreads();
    const float* Hb = H + ((size_t)b * NN + k0) * NN + j;
    __half* hi = g_Hhi + ((size_t)b * NN + k0) * NN + j;
    __half* lo = g_Hlo + ((size_t)b * NN + k0) * NN + j;
    float yh = 0.f, hh = 0.f;
#pragma unroll 4
    for (int i = 0; i < 128; ++i) {
        float h = Hb[(size_t)i * NN];
        __half hb = __float2half(h);
        hi[(size_t)i * NN] = hb;
        lo[(size_t)i * NN] = __float2half(h - __half2float(hb));
        yh += sy[i] * h;
        hh += h * h;
    }
    int node = b * NN + j;
    g_yhp[blockIdx.z * NNODE + node] = yh;
    g_hhp[blockIdx.z * NNODE + node] = hh;
}

// -------- adj pass: neighbor lists + deg + fp16 adj + zero-init --------
__global__ void k_csr(const float* __restrict__ adj) {
    int row  = blockIdx.x * (blockDim.x >> 5) + (threadIdx.x >> 5);
    int lane = threadIdx.x & 31;
    const float* ar = adj + (size_t)row * NN;
    __half* ah = g_adjh + (size_t)row * NN;
    const __half ONE = __float2half(1.f), ZERO = __float2half(0.f);
    int base = row * MAXN;
    int boff = (row >> 10) << 10;
    int cnt  = 0;
    for (int c = 0; c < NN; c += 32) {
        float a = ar[c + lane];
        ah[c + lane] = (a != 0.f) ? ONE : ZERO;
        unsigned m = __ballot_sync(FULL, a != 0.f);
        if (a != 0.f) {
            int pos = cnt + __popc(m & ((1u << lane) - 1u));
            if (pos < MAXN) g_nbru[base + pos] = (boff + c + lane) * 8;
        }
        cnt += __popc(m);
    }
    int cntc = cnt < MAXN ? cnt : MAXN;
    int cntp = (cntc + 3) & ~3;   // pad to x4 for 4-lane gather
    if (lane < cntp - cntc) g_nbru[base + cntc + lane] = NNODE * 8;  // zero u row
    if (lane == 0) {
        g_cnt[row] = cntc;
        g_deg[row] = (float)cnt;
        g_eg[row]  = 0.f;
    }
    if (lane < 12) g_s[(size_t)row * 12 + lane] = 0.f;
    if (row == 0 && lane < 8) { g_u[0][NNODE * 8 + lane] = 0.f; g_u[1][NNODE * 8 + lane] = 0.f; }
}

// -------- eg via mma.sync: T = (Hhi+Hlo) @ adj^T, eg_i = sum_k H[k,i]*T[k,i] --
// 64-wide K chunks (16 barriers), 2-stage cp.async, ldmatrix fragments.
static const int TSTRIDE = 144;             // bytes per tile row (64 halves + pad)
static const int TILEB   = 128 * TSTRIDE;   // 18432 B per tile
static const int STAGEB  = 3 * TILEB;       // Ahi, Alo, B per stage = 55296 B

__global__ void __launch_bounds__(256, 2) k_gemm(const float* __restrict__ H,
                                                 const float* __restrict__ W1w,
                                                 const float* __restrict__ W1b,
                                                 const float* __restrict__ b1) {
    extern __shared__ __align__(16) char smb[];
    const int tid = threadIdx.x, wid = tid >> 5, lane = tid & 31;
    const int g = lane >> 2, t = lane & 3;
    const int b = blockIdx.z;
    const int i0 = blockIdx.x * 128, k0 = blockIdx.y * 128;
    const int wm = wid & 1, wn = wid >> 1;

    // u0 = W1([yh,hh]) finalize on the 128 blocks with blockIdx.y==0
    if (blockIdx.y == 0 && tid < 128) {
        int node = (b * 8 + blockIdx.x) * 128 + tid;
        float yh = 0.f, hh = 0.f;
#pragma unroll
        for (int z = 0; z < 8; ++z) {
            yh += g_yhp[z * NNODE + node];
            hh += g_hhp[z * NNODE + node];
        }
        float* up = &g_u[0][(size_t)node * 8];
#pragma unroll
        for (int c = 0; c < 8; ++c)
            up[c] = W1w[2 * c] * yh + W1w[2 * c + 1] * hh + W1b[c] + b1[c];
    }

    const __half* Ahi = g_Hhi  + ((size_t)b * NN + k0) * NN;
    const __half* Alo = g_Hlo  + ((size_t)b * NN + k0) * NN;
    const __half* Bad = g_adjh + ((size_t)b * NN + i0) * NN;
    const uint32_t sbase = sm_u32(smb);

    const int arow = (lane & 7) + ((lane >> 3) & 1) * 8;
    const int acol = (lane >> 4) * 16;
    const int brow = (lane & 7) + (lane >> 4) * 8;
    const int bcol = ((lane >> 3) & 1) * 16;

    float acc[4][4][4];
#pragma unroll
    for (int a = 0; a < 4; ++a)
#pragma unroll
        for (int n = 0; n < 4; ++n)
#pragma unroll
            for (int r = 0; r < 4; ++r) acc[a][n][r] = 0.f;

    // cp.async fill: chunk c (64 k-cols) into buffer c&1
    auto issue = [&](int c) {
        int j0 = c * 64;
        uint32_t tb = sbase + (c & 1) * STAGEB;
#pragma unroll
        for (int q = 0; q < 4; ++q) {
            int idx = tid + q * 256;
            int row = idx >> 3, quad = idx & 7;
            uint32_t so = tb + row * TSTRIDE + quad * 16;
            cpasync16(so,             Ahi + (size_t)row * NN + j0 + quad * 8);
            cpasync16(so + TILEB,     Alo + (size_t)row * NN + j0 + quad * 8);
            cpasync16(so + 2 * TILEB, Bad + (size_t)row * NN + j0 + quad * 8);
        }
        asm volatile("cp.async.commit_group;" ::: "memory");
    };

    issue(0);
    for (int c = 0; c < 16; ++c) {
        asm volatile("cp.async.wait_group 0;" ::: "memory");
        __syncthreads();                 // all warps done with buffer (c-1)&1
        if (c < 15) issue(c + 1);        // prefetch next chunk during compute
        uint32_t sA = sbase + (c & 1) * STAGEB;
        uint32_t sL = sA + TILEB, sB = sA + 2 * TILEB;
#pragma unroll
        for (int ks = 0; ks < 4; ++ks) {
            uint32_t bfr[4][2];
            ldsm4(bfr[0][0], bfr[0][1], bfr[1][0], bfr[1][1],
                  sB + (wn * 32 + brow) * TSTRIDE + ks * 32 + bcol);
            ldsm4(bfr[2][0], bfr[2][1], bfr[3][0], bfr[3][1],
                  sB + (wn * 32 + 16 + brow) * TSTRIDE + ks * 32 + bcol);
#pragma unroll
            for (int sp = 0; sp < 2; ++sp) {
                uint32_t sa = sp ? sL : sA;
#pragma unroll
                for (int mi = 0; mi < 4; ++mi) {
                    uint32_t a0, a1, a2, a3;
                    ldsm4(a0, a1, a2, a3,
                          sa + (wm * 64 + mi * 16 + arow) * TSTRIDE + ks * 32 + acol);
#pragma unroll
                    for (int ni = 0; ni < 4; ++ni)
                        mma16816(acc[mi][ni], a0, a1, a2, a3, bfr[ni][0], bfr[ni][1]);
                }
            }
        }
        __syncthreads();                 // compute done before next overwrite
    }

    const float* Hb = H + ((size_t)b * NN + k0) * NN + i0;
#pragma unroll
    for (int ni = 0; ni < 4; ++ni) {
        int col = wn * 32 + ni * 8 + 2 * t;
        float p0 = 0.f, p1 = 0.f;
#pragma unroll
        for (int mi = 0; mi < 4; ++mi) {
            int m = wm * 64 + mi * 16;
            float2 h0 = *(const float2*)(Hb + (size_t)(m + g) * NN + col);
            float2 h1 = *(const float2*)(Hb + (size_t)(m + g + 8) * NN + col);
            p0 += acc[mi][ni][0] * h0.x + acc[mi][ni][2] * h1.x;
            p1 += acc[mi][ni][1] * h0.y + acc[mi][ni][3] * h1.y;
        }
#pragma unroll
        for (int o = 4; o < 32; o <<= 1) {
            p0 += __shfl_xor_sync(FULL, p0, o);
            p1 += __shfl_xor_sync(FULL, p1, o);
        }
        if (g == 0) {
            atomicAdd(&g_eg[b * NN + i0 + col], p0);
            atomicAdd(&g_eg[b * NN + i0 + col + 1], p1);
        }
    }
}

// -------- fused per-node: 2-phase (128-thread gather, warp-0 compute) ------
__global__ void k_node(const float* __restrict__ r, const float* __restrict__ nur,
                       const float* __restrict__ Wm1, const float* __restrict__ Wm1b,
                       const float* __restrict__ Wm2, const float* __restrict__ Wm2b,
                       const float* __restrict__ wih, const float* __restrict__ whh,
                       const float* __restrict__ bih, const float* __restrict__ bhh,
                       const float* __restrict__ W2,  const float* __restrict__ W2b,
                       const float* __restrict__ b2,
                       const float* __restrict__ Wr1, const float* __restrict__ Wr1b,
                       const float* __restrict__ Wr2, const float* __restrict__ Wr2b,
                       int bufin, int last, float* __restrict__ out) {
    __shared__ float w[1690];
    __shared__ float sns[32][9];
    {
        int t = threadIdx.x;
        for (int i = t; i < 384; i += blockDim.x) w[i]        = Wm1[i];
        for (int i = t; i < 16;  i += blockDim.x) w[384 + i]  = Wm1b[i];
        for (int i = t; i < 128; i += blockDim.x) w[400 + i]  = Wm2[i];
        for (int i = t; i < 8;   i += blockDim.x) w[528 + i]  = Wm2b[i];
        for (int i = t; i < 360; i += blockDim.x) w[536 + i]  = wih[i];
        for (int i = t; i < 432; i += blockDim.x) w[896 + i]  = whh[i];
        for (int i = t; i < 36;  i += blockDim.x) w[1328 + i] = bih[i];
        for (int i = t; i < 36;  i += blockDim.x) w[1364 + i] = bhh[i];
        for (int i = t; i < 96;  i += blockDim.x) w[1400 + i] = W2[i];
        for (int i = t; i < 8;   i += blockDim.x) w[1496 + i] = W2b[i] + b2[i];
        for (int i = t; i < 128; i += blockDim.x) w[1512 + i] = Wr1[i];
        for (int i = t; i < 16;  i += blockDim.x) w[1640 + i] = Wr1b[i];
        for (int i = t; i < 32;  i += blockDim.x) w[1656 + i] = Wr2[i];
        for (int i = t; i < 2;   i += blockDim.x) w[1688 + i] = Wr2b[i];
    }
    __syncthreads();
    const float* uin = g_u[bufin];
    float* uout = g_u[bufin ^ 1];

    // ---- phase 1: gather (4 lanes per node, 32 nodes per block) ----
    {
        int q    = threadIdx.x & 3;
        int nib  = threadIdx.x >> 2;
        int node = blockIdx.x * 32 + nib;
        float ns[8] = {0, 0, 0, 0, 0, 0, 0, 0};
        int nq = ((g_cnt[node] + 3) & ~3) >> 2;
        const int4* off = (const int4*)&g_nbru[node * MAXN];
        for (int i = q; i < nq; i += 4) {
            int4 o = off[i];
            const float4* p0 = (const float4*)(uin + o.x);
            const float4* p1 = (const float4*)(uin + o.y);
            const float4* p2 = (const float4*)(uin + o.z);
            const float4* p3 = (const float4*)(uin + o.w);
            float4 a0 = p0[0], b0 = p0[1];
            float4 a1 = p1[0], b1 = p1[1];
            float4 a2 = p2[0], b2v = p2[1];
            float4 a3 = p3[0], b3 = p3[1];
            ns[0] += a0.x + a1.x + a2.x + a3.x;
            ns[1] += a0.y + a1.y + a2.y + a3.y;
            ns[2] += a0.z + a1.z + a2.z + a3.z;
            ns[3] += a0.w + a1.w + a2.w + a3.w;
            ns[4] += b0.x + b1.x + b2v.x + b3.x;
            ns[5] += b0.y + b1.y + b2v.y + b3.y;
            ns[6] += b0.z + b1.z + b2v.z + b3.z;
            ns[7] += b0.w + b1.w + b2v.w + b3.w;
        }
#pragma unroll
        for (int c = 0; c < 8; ++c) {
            ns[c] += __shfl_xor_sync(FULL, ns[c], 1);
            ns[c] += __shfl_xor_sync(FULL, ns[c], 2);
        }
        if (q == 0) {
#pragma unroll
            for (int c = 0; c < 8; ++c) sns[nib][c] = ns[c];
        }
    }
    __syncthreads();
    if (threadIdx.x >= 32) return;

    // ---- phase 2: warp 0, one node per lane, all lanes active ----
    int lane = threadIdx.x;
    int node = blockIdx.x * 32 + lane;

    float ns[8];
#pragma unroll
    for (int c = 0; c < 8; ++c) ns[c] = sns[lane][c];

    float rv  = r[node];
    float nuv = fmaxf(nur[node], 1e-10f);
    float deg = g_deg[node], eg = g_eg[node];

    float u[8];
    {
        const float4* up = (const float4*)(uin + (size_t)node * 8);
        float4 a = up[0], b4 = up[1];
        u[0] = a.x; u[1] = a.y; u[2] = a.z; u[3] = a.w;
        u[4] = b4.x; u[5] = b4.y; u[6] = b4.z; u[7] = b4.w;
    }

    float m[8];
    {
        float hid[16];
#pragma unroll
        for (int t = 0; t < 16; ++t) {
            float h = w[384 + t];
#pragma unroll
            for (int c = 0; c < 8; ++c) h += w[t * 24 + c] * (u[c] * deg);
#pragma unroll
            for (int c = 0; c < 8; ++c) h += w[t * 24 + 8 + c] * ns[c];
#pragma unroll
            for (int c = 0; c < 8; ++c) h += w[t * 24 + 16 + c] * eg;
            hid[t] = fmaxf(h, 0.f);
        }
#pragma unroll
        for (int o = 0; o < 8; ++o) {
            float v = w[528 + o];
#pragma unroll
            for (int t = 0; t < 16; ++t) v += w[400 + o * 16 + t] * hid[t];
            m[o] = v;
        }
    }

    float x[10];
#pragma unroll
    for (int c = 0; c < 8; ++c) x[c] = m[c];
    x[8] = rv;
    x[9] = nuv;

    float s[12];
#pragma unroll
    for (int c = 0; c < 12; ++c) s[c] = g_s[(size_t)node * 12 + c];

    float sn[12];
#pragma unroll
    for (int g = 0; g < 12; ++g) {
        float xr = w[1328 + g], xz = w[1328 + 12 + g], xn = w[1328 + 24 + g];
#pragma unroll
        for (int c = 0; c < 10; ++c) {
            float xv = x[c];
            xr += w[536 + g * 10 + c] * xv;
            xz += w[536 + (12 + g) * 10 + c] * xv;
            xn += w[536 + (24 + g) * 10 + c] * xv;
        }
        float hr = w[1364 + g], hz = w[1364 + 12 + g], hn = w[1364 + 24 + g];
#pragma unroll
        for (int c = 0; c < 12; ++c) {
            float sv = s[c];
            hr += w[896 + g * 12 + c] * sv;
            hz += w[896 + (12 + g) * 12 + c] * sv;
            hn += w[896 + (24 + g) * 12 + c] * sv;
        }
        float rg = sigf(xr + hr);
        float zg = sigf(xz + hz);
        float ng = tanhff(xn + rg * hn);
        sn[g] = (1.f - zg) * ng + zg * s[g];
    }
#pragma unroll
    for (int c = 0; c < 12; ++c) g_s[(size_t)node * 12 + c] = sn[c];

    float un[8];
#pragma unroll
    for (int o = 0; o < 8; ++o) {
        float v = w[1496 + o];
#pragma unroll
        for (int c = 0; c < 12; ++c) v += w[1400 + o * 12 + c] * sn[c];
        un[o] = v;
    }
    {
        float4* op = (float4*)(uout + (size_t)node * 8);
        op[0] = make_float4(un[0], un[1], un[2], un[3]);
        op[1] = make_float4(un[4], un[5], un[6], un[7]);
    }

    if (last) {
        float hid[16];
#pragma unroll
        for (int t = 0; t < 16; ++t) {
            float h = w[1640 + t];
#pragma unroll
            for (int c = 0; c < 8; ++c) h += w[1512 + t * 8 + c] * un[c];
            hid[t] = fmaxf(h, 0.f);
        }
        float l0 = w[1688], l1 = w[1689];
#pragma unroll
        for (int t = 0; t < 16; ++t) {
            l0 += w[1656 + t] * hid[t];
            l1 += w[1656 + 16 + t] * hid[t];
        }
        float mx = fmaxf(l0, l1);
        float e0 = __expf(l0 - mx), e1 = __expf(l1 - mx);
        float inv = __fdividef(1.f, e0 + e1);
        float p0 = e0 * inv, p1 = e1 * inv;
        const float q0 = -0.70710678118654752440f, q1 = 0.70710678118654752440f;
        float xh = p0 * q0 + p1 * q1;
        float nu = p0 * (q0 - xh) * (q0 - xh) + p1 * (q1 - xh) * (q1 - xh);
        nu = fmaxf(nu, 1e-10f);
        out[node]         = xh;
        out[NNODE + node] = nu;
    }
}

extern "C" void kernel_launch(void* const* d_in, const int* in_sizes, int n_in,
                              void* d_out, int out_size) {
    const float* y    = (const float*)d_in[0];
    const float* H    = (const float*)d_in[1];
    const float* r    = (const float*)d_in[2];
    const float* nur  = (const float*)d_in[3];
    const float* adj  = (const float*)d_in[4];
    const float* W1w  = (const float*)d_in[5];
    const float* W1b  = (const float*)d_in[6];
    const float* b1   = (const float*)d_in[7];
    const float* Wm1  = (const float*)d_in[8];
    const float* Wm1b = (const float*)d_in[9];
    const float* Wm2  = (const float*)d_in[10];
    const float* Wm2b = (const float*)d_in[11];
    const float* wih  = (const float*)d_in[12];
    const float* whh  = (const float*)d_in[13];
    const float* bih  = (const float*)d_in[14];
    const float* bhh  = (const float*)d_in[15];
    const float* W2   = (const float*)d_in[16];
    const float* W2b  = (const float*)d_in[17];
    const float* b2   = (const float*)d_in[18];
    const float* Wr1  = (const float*)d_in[19];
    const float* Wr1b = (const float*)d_in[20];
    const float* Wr2  = (const float*)d_in[21];
    const float* Wr2b = (const float*)d_in[22];
    float* out = (float*)d_out;

    const int GEMM_SMEM = 2 * STAGEB;   // 110592 B
    cudaFuncSetAttribute(k_gemm, cudaFuncAttributeMaxDynamicSharedMemorySize, GEMM_SMEM);

    // fork: k_convcol (H pass) on side stream, k_csr (adj pass) on main stream
    cudaStream_t s2;
    cudaStreamCreateWithFlags(&s2, cudaStreamNonBlocking);
    cudaEvent_t evF, evJ;
    cudaEventCreateWithFlags(&evF, cudaEventDisableTiming);
    cudaEventCreateWithFlags(&evJ, cudaEventDisableTiming);
    cudaEventRecord(evF, 0);
    cudaStreamWaitEvent(s2, evF, 0);
    k_convcol<<<dim3(NB, NN / 128, 8), 128, 0, s2>>>(H, y);
    k_csr<<<NNODE / 8, 256>>>(adj);
    cudaEventRecord(evJ, s2);
    cudaStreamWaitEvent(0, evJ, 0);

    k_gemm<<<dim3(8, 8, NB), 256, GEMM_SMEM>>>(H, W1w, W1b, b1);
    k_node<<<NNODE / 32, 128>>>(r, nur, Wm1, Wm1b, Wm2, Wm2b, wih, whh, bih, bhh,
                                W2, W2b, b2, Wr1, Wr1b, Wr2, Wr2b, 0, 0, out);
    k_node<<<NNODE / 32, 128>>>(r, nur, Wm1, Wm1b, Wm2, Wm2b, wih, whh, bih, bhh,
                                W2, W2b, b2, Wr1, Wr1b, Wr2, Wr2b, 1, 1, out);

    cudaEventDestroy(evF);
    cudaEventDestroy(evJ);
    cudaStreamDestroy(s2);
}

// round 14
// speedup vs baseline: 1.1150x; 1.0194x over previous
#include <cuda_runtime.h>
#include <cuda_fp16.h>
#include <stdint.h>
#include <math.h>

#define FULL 0xffffffffu

static const int NB    = 16;
static const int NN    = 1024;
static const int NNODE = NB * NN;   // 16384
static const int MAXN  = 192;
static const int NWELT = 1690;

// -------- static device scratch (no allocations allowed) --------
__device__ float g_u[2][NNODE * 8 + 8];
__device__ float g_s[NNODE * 12];
__device__ float g_yhp[8 * NNODE];
__device__ float g_hhp[8 * NNODE];
__device__ float g_deg[NNODE];
__device__ float g_eg[NNODE];
__device__ int   g_nbru[NNODE * MAXN];
__device__ int   g_cnt[NNODE];
__device__ float g_wpack[NWELT];
__device__ __half g_Hhi[(size_t)NB * NN * NN];
__device__ __half g_Hlo[(size_t)NB * NN * NN];
__device__ __half g_adjh[(size_t)NB * NN * NN];

__constant__ float c_w[NWELT];   // packed k_node weights (const-bank operands)

__device__ __forceinline__ uint32_t sm_u32(const void* p) {
    uint32_t a;
    asm("{ .reg .u64 t; cvta.to.shared.u64 t, %1; cvt.u32.u64 %0, t; }"
        : "=r"(a) : "l"(p));
    return a;
}
__device__ __forceinline__ void cpasync16(uint32_t dst, const void* src) {
    asm volatile("cp.async.cg.shared.global [%0], [%1], 16;"
                 :: "r"(dst), "l"(src) : "memory");
}
__device__ __forceinline__ void ldsm4(uint32_t& r0, uint32_t& r1, uint32_t& r2,
                                      uint32_t& r3, uint32_t a) {
    asm volatile("ldmatrix.sync.aligned.m8n8.x4.shared.b16 {%0,%1,%2,%3}, [%4];"
                 : "=r"(r0), "=r"(r1), "=r"(r2), "=r"(r3) : "r"(a));
}
__device__ __forceinline__ void mma16816(float* c, uint32_t a0, uint32_t a1,
                                         uint32_t a2, uint32_t a3,
                                         uint32_t b0, uint32_t b1) {
    asm volatile(
        "mma.sync.aligned.m16n8k16.row.col.f32.f16.f16.f32 "
        "{%0,%1,%2,%3}, {%4,%5,%6,%7}, {%8,%9}, {%0,%1,%2,%3};"
        : "+f"(c[0]), "+f"(c[1]), "+f"(c[2]), "+f"(c[3])
        : "r"(a0), "r"(a1), "r"(a2), "r"(a3), "r"(b0), "r"(b1));
}

// fast activations (HW EX2/RCP paths, clamped against overflow)
__device__ __forceinline__ float sigf(float x) {
    float e = __expf(-fmaxf(x, -80.f));
    return __fdividef(1.f, 1.f + e);
}
__device__ __forceinline__ float tanhff(float x) {
    float xc = fminf(fmaxf(x, -15.f), 15.f);
    float t  = __expf(2.f * xc);
    return __fdividef(t - 1.f, t + 1.f);
}

// -------- one pass over H: yh/hh partials + fp16 hi/lo split --------
__global__ void k_convcol(const float* __restrict__ H, const float* __restrict__ y) {
    __shared__ float sy[128];
    int b = blockIdx.x, j = blockIdx.y * 128 + threadIdx.x, k0 = blockIdx.z * 128;
    sy[threadIdx.x] = y[b * NN + k0 + threadIdx.x];
    __syncthreads();
    const float* Hb = H + ((size_t)b * NN + k0) * NN + j;
    __half* hi = g_Hhi + ((size_t)b * NN + k0) * NN + j;
    __half* lo = g_Hlo + ((size_t)b * NN + k0) * NN + j;
    float yh = 0.f, hh = 0.f;
#pragma unroll 4
    for (int i = 0; i < 128; ++i) {
        float h = Hb[(size_t)i * NN];
        __half hb = __float2half(h);
        hi[(size_t)i * NN] = hb;
        lo[(size_t)i * NN] = __float2half(h - __half2float(hb));
        yh += sy[i] * h;
        hh += h * h;
    }
    int node = b * NN + j;
    g_yhp[blockIdx.z * NNODE + node] = yh;
    g_hhp[blockIdx.z * NNODE + node] = hh;
}

// -------- adj pass: neighbor lists + deg + fp16 adj + zero-init + w-pack ----
__global__ void k_csr(const float* __restrict__ adj,
                      const float* __restrict__ Wm1, const float* __restrict__ Wm1b,
                      const float* __restrict__ Wm2, const float* __restrict__ Wm2b,
                      const float* __restrict__ wih, const float* __restrict__ whh,
                      const float* __restrict__ bih, const float* __restrict__ bhh,
                      const float* __restrict__ W2,  const float* __restrict__ W2b,
                      const float* __restrict__ b2,
                      const float* __restrict__ Wr1, const float* __restrict__ Wr1b,
                      const float* __restrict__ Wr2, const float* __restrict__ Wr2b) {
    if (blockIdx.x == 0) {   // pack k_node weights into staging buffer
        int t = threadIdx.x;
        for (int i = t; i < 384; i += 256) g_wpack[i]        = Wm1[i];
        for (int i = t; i < 16;  i += 256) g_wpack[384 + i]  = Wm1b[i];
        for (int i = t; i < 128; i += 256) g_wpack[400 + i]  = Wm2[i];
        for (int i = t; i < 8;   i += 256) g_wpack[528 + i]  = Wm2b[i];
        for (int i = t; i < 360; i += 256) g_wpack[536 + i]  = wih[i];
        for (int i = t; i < 432; i += 256) g_wpack[896 + i]  = whh[i];
        for (int i = t; i < 36;  i += 256) g_wpack[1328 + i] = bih[i];
        for (int i = t; i < 36;  i += 256) g_wpack[1364 + i] = bhh[i];
        for (int i = t; i < 96;  i += 256) g_wpack[1400 + i] = W2[i];
        for (int i = t; i < 8;   i += 256) g_wpack[1496 + i] = W2b[i] + b2[i];
        for (int i = t; i < 128; i += 256) g_wpack[1512 + i] = Wr1[i];
        for (int i = t; i < 16;  i += 256) g_wpack[1640 + i] = Wr1b[i];
        for (int i = t; i < 32;  i += 256) g_wpack[1656 + i] = Wr2[i];
        for (int i = t; i < 2;   i += 256) g_wpack[1688 + i] = Wr2b[i];
    }
    int row  = blockIdx.x * (blockDim.x >> 5) + (threadIdx.x >> 5);
    int lane = threadIdx.x & 31;
    const float* ar = adj + (size_t)row * NN;
    __half* ah = g_adjh + (size_t)row * NN;
    const __half ONE = __float2half(1.f), ZERO = __float2half(0.f);
    int base = row * MAXN;
    int boff = (row >> 10) << 10;
    int cnt  = 0;
    for (int c = 0; c < NN; c += 32) {
        float a = ar[c + lane];
        ah[c + lane] = (a != 0.f) ? ONE : ZERO;
        unsigned m = __ballot_sync(FULL, a != 0.f);
        if (a != 0.f) {
            int pos = cnt + __popc(m & ((1u << lane) - 1u));
            if (pos < MAXN) g_nbru[base + pos] = (boff + c + lane) * 8;
        }
        cnt += __popc(m);
    }
    int cntc = cnt < MAXN ? cnt : MAXN;
    int cntp = (cntc + 3) & ~3;   // pad to x4 for 4-lane gather
    if (lane < cntp - cntc) g_nbru[base + cntc + lane] = NNODE * 8;  // zero u row
    if (lane == 0) {
        g_cnt[row] = cntc;
        g_deg[row] = (float)cnt;
        g_eg[row]  = 0.f;
    }
    if (lane < 12) g_s[(size_t)row * 12 + lane] = 0.f;
    if (row == 0 && lane < 8) { g_u[0][NNODE * 8 + lane] = 0.f; g_u[1][NNODE * 8 + lane] = 0.f; }
}

// -------- eg via mma.sync: T = (Hhi+Hlo) @ adj^T, eg_i = sum_k H[k,i]*T[k,i] --
// 64-wide K chunks (16 barriers), 2-stage cp.async, ldmatrix fragments.
static const int TSTRIDE = 144;             // bytes per tile row (64 halves + pad)
static const int TILEB   = 128 * TSTRIDE;   // 18432 B per tile
static const int STAGEB  = 3 * TILEB;       // Ahi, Alo, B per stage = 55296 B

__global__ void __launch_bounds__(256, 2) k_gemm(const float* __restrict__ H,
                                                 const float* __restrict__ W1w,
                                                 const float* __restrict__ W1b,
                                                 const float* __restrict__ b1) {
    extern __shared__ __align__(16) char smb[];
    const int tid = threadIdx.x, wid = tid >> 5, lane = tid & 31;
    const int g = lane >> 2, t = lane & 3;
    const int b = blockIdx.z;
    const int i0 = blockIdx.x * 128, k0 = blockIdx.y * 128;
    const int wm = wid & 1, wn = wid >> 1;

    // u0 = W1([yh,hh]) finalize on the 128 blocks with blockIdx.y==0
    if (blockIdx.y == 0 && tid < 128) {
        int node = (b * 8 + blockIdx.x) * 128 + tid;
        float yh = 0.f, hh = 0.f;
#pragma unroll
        for (int z = 0; z < 8; ++z) {
            yh += g_yhp[z * NNODE + node];
            hh += g_hhp[z * NNODE + node];
        }
        float* up = &g_u[0][(size_t)node * 8];
#pragma unroll
        for (int c = 0; c < 8; ++c)
            up[c] = W1w[2 * c] * yh + W1w[2 * c + 1] * hh + W1b[c] + b1[c];
    }

    const __half* Ahi = g_Hhi  + ((size_t)b * NN + k0) * NN;
    const __half* Alo = g_Hlo  + ((size_t)b * NN + k0) * NN;
    const __half* Bad = g_adjh + ((size_t)b * NN + i0) * NN;
    const uint32_t sbase = sm_u32(smb);

    const int arow = (lane & 7) + ((lane >> 3) & 1) * 8;
    const int acol = (lane >> 4) * 16;
    const int brow = (lane & 7) + (lane >> 4) * 8;
    const int bcol = ((lane >> 3) & 1) * 16;

    float acc[4][4][4];
#pragma unroll
    for (int a = 0; a < 4; ++a)
#pragma unroll
        for (int n = 0; n < 4; ++n)
#pragma unroll
            for (int r = 0; r < 4; ++r) acc[a][n][r] = 0.f;

    // cp.async fill: chunk c (64 k-cols) into buffer c&1
    auto issue = [&](int c) {
        int j0 = c * 64;
        uint32_t tb = sbase + (c & 1) * STAGEB;
#pragma unroll
        for (int q = 0; q < 4; ++q) {
            int idx = tid + q * 256;
            int row = idx >> 3, quad = idx & 7;
            uint32_t so = tb + row * TSTRIDE + quad * 16;
            cpasync16(so,             Ahi + (size_t)row * NN + j0 + quad * 8);
            cpasync16(so + TILEB,     Alo + (size_t)row * NN + j0 + quad * 8);
            cpasync16(so + 2 * TILEB, Bad + (size_t)row * NN + j0 + quad * 8);
        }
        asm volatile("cp.async.commit_group;" ::: "memory");
    };

    issue(0);
    for (int c = 0; c < 16; ++c) {
        asm volatile("cp.async.wait_group 0;" ::: "memory");
        __syncthreads();                 // all warps done with buffer (c-1)&1
        if (c < 15) issue(c + 1);        // prefetch next chunk during compute
        uint32_t sA = sbase + (c & 1) * STAGEB;
        uint32_t sL = sA + TILEB, sB = sA + 2 * TILEB;
#pragma unroll
        for (int ks = 0; ks < 4; ++ks) {
            uint32_t bfr[4][2];
            ldsm4(bfr[0][0], bfr[0][1], bfr[1][0], bfr[1][1],
                  sB + (wn * 32 + brow) * TSTRIDE + ks * 32 + bcol);
            ldsm4(bfr[2][0], bfr[2][1], bfr[3][0], bfr[3][1],
                  sB + (wn * 32 + 16 + brow) * TSTRIDE + ks * 32 + bcol);
#pragma unroll
            for (int sp = 0; sp < 2; ++sp) {
                uint32_t sa = sp ? sL : sA;
#pragma unroll
                for (int mi = 0; mi < 4; ++mi) {
                    uint32_t a0, a1, a2, a3;
                    ldsm4(a0, a1, a2, a3,
                          sa + (wm * 64 + mi * 16 + arow) * TSTRIDE + ks * 32 + acol);
#pragma unroll
                    for (int ni = 0; ni < 4; ++ni)
                        mma16816(acc[mi][ni], a0, a1, a2, a3, bfr[ni][0], bfr[ni][1]);
                }
            }
        }
        __syncthreads();                 // compute done before next overwrite
    }

    const float* Hb = H + ((size_t)b * NN + k0) * NN + i0;
#pragma unroll
    for (int ni = 0; ni < 4; ++ni) {
        int col = wn * 32 + ni * 8 + 2 * t;
        float p0 = 0.f, p1 = 0.f;
#pragma unroll
        for (int mi = 0; mi < 4; ++mi) {
            int m = wm * 64 + mi * 16;
            float2 h0 = *(const float2*)(Hb + (size_t)(m + g) * NN + col);
            float2 h1 = *(const float2*)(Hb + (size_t)(m + g + 8) * NN + col);
            p0 += acc[mi][ni][0] * h0.x + acc[mi][ni][2] * h1.x;
            p1 += acc[mi][ni][1] * h0.y + acc[mi][ni][3] * h1.y;
        }
#pragma unroll
        for (int o = 4; o < 32; o <<= 1) {
            p0 += __shfl_xor_sync(FULL, p0, o);
            p1 += __shfl_xor_sync(FULL, p1, o);
        }
        if (g == 0) {
            atomicAdd(&g_eg[b * NN + i0 + col], p0);
            atomicAdd(&g_eg[b * NN + i0 + col + 1], p1);
        }
    }
}

// -------- fused per-node: 2-phase (128-thread gather, warp-0 compute) ------
// Weights come from __constant__ c_w: const-bank FFMA operands, no LDS.
__global__ void k_node(const float* __restrict__ r, const float* __restrict__ nur,
                       int bufin, int last, float* __restrict__ out) {
    __shared__ float sns[32][9];
    const float* uin = g_u[bufin];
    float* uout = g_u[bufin ^ 1];

    // ---- phase 1: gather (4 lanes per node, 32 nodes per block) ----
    {
        int q    = threadIdx.x & 3;
        int nib  = threadIdx.x >> 2;
        int node = blockIdx.x * 32 + nib;
        float ns[8] = {0, 0, 0, 0, 0, 0, 0, 0};
        int nq = ((g_cnt[node] + 3) & ~3) >> 2;
        const int4* off = (const int4*)&g_nbru[node * MAXN];
        for (int i = q; i < nq; i += 4) {
            int4 o = off[i];
            const float4* p0 = (const float4*)(uin + o.x);
            const float4* p1 = (const float4*)(uin + o.y);
            const float4* p2 = (const float4*)(uin + o.z);
            const float4* p3 = (const float4*)(uin + o.w);
            float4 a0 = p0[0], b0 = p0[1];
            float4 a1 = p1[0], b1 = p1[1];
            float4 a2 = p2[0], b2v = p2[1];
            float4 a3 = p3[0], b3 = p3[1];
            ns[0] += a0.x + a1.x + a2.x + a3.x;
            ns[1] += a0.y + a1.y + a2.y + a3.y;
            ns[2] += a0.z + a1.z + a2.z + a3.z;
            ns[3] += a0.w + a1.w + a2.w + a3.w;
            ns[4] += b0.x + b1.x + b2v.x + b3.x;
            ns[5] += b0.y + b1.y + b2v.y + b3.y;
            ns[6] += b0.z + b1.z + b2v.z + b3.z;
            ns[7] += b0.w + b1.w + b2v.w + b3.w;
        }
#pragma unroll
        for (int c = 0; c < 8; ++c) {
            ns[c] += __shfl_xor_sync(FULL, ns[c], 1);
            ns[c] += __shfl_xor_sync(FULL, ns[c], 2);
        }
        if (q == 0) {
#pragma unroll
            for (int c = 0; c < 8; ++c) sns[nib][c] = ns[c];
        }
    }
    __syncthreads();
    if (threadIdx.x >= 32) return;

    // ---- phase 2: warp 0, one node per lane, all lanes active ----
    int lane = threadIdx.x;
    int node = blockIdx.x * 32 + lane;

    float ns[8];
#pragma unroll
    for (int c = 0; c < 8; ++c) ns[c] = sns[lane][c];

    float rv  = r[node];
    float nuv = fmaxf(nur[node], 1e-10f);
    float deg = g_deg[node], eg = g_eg[node];

    float u[8];
    {
        const float4* up = (const float4*)(uin + (size_t)node * 8);
        float4 a = up[0], b4 = up[1];
        u[0] = a.x; u[1] = a.y; u[2] = a.z; u[3] = a.w;
        u[4] = b4.x; u[5] = b4.y; u[6] = b4.z; u[7] = b4.w;
    }

    float m[8];
    {
        float hid[16];
#pragma unroll
        for (int t = 0; t < 16; ++t) {
            float h = c_w[384 + t];
#pragma unroll
            for (int c = 0; c < 8; ++c) h += c_w[t * 24 + c] * (u[c] * deg);
#pragma unroll
            for (int c = 0; c < 8; ++c) h += c_w[t * 24 + 8 + c] * ns[c];
#pragma unroll
            for (int c = 0; c < 8; ++c) h += c_w[t * 24 + 16 + c] * eg;
            hid[t] = fmaxf(h, 0.f);
        }
#pragma unroll
        for (int o = 0; o < 8; ++o) {
            float v = c_w[528 + o];
#pragma unroll
            for (int t = 0; t < 16; ++t) v += c_w[400 + o * 16 + t] * hid[t];
            m[o] = v;
        }
    }

    float x[10];
#pragma unroll
    for (int c = 0; c < 8; ++c) x[c] = m[c];
    x[8] = rv;
    x[9] = nuv;

    float s[12];
#pragma unroll
    for (int c = 0; c < 12; ++c) s[c] = g_s[(size_t)node * 12 + c];

    float sn[12];
#pragma unroll
    for (int g = 0; g < 12; ++g) {
        float xr = c_w[1328 + g], xz = c_w[1328 + 12 + g], xn = c_w[1328 + 24 + g];
#pragma unroll
        for (int c = 0; c < 10; ++c) {
            float xv = x[c];
            xr += c_w[536 + g * 10 + c] * xv;
            xz += c_w[536 + (12 + g) * 10 + c] * xv;
            xn += c_w[536 + (24 + g) * 10 + c] * xv;
        }
        float hr = c_w[1364 + g], hz = c_w[1364 + 12 + g], hn = c_w[1364 + 24 + g];
#pragma unroll
        for (int c = 0; c < 12; ++c) {
            float sv = s[c];
            hr += c_w[896 + g * 12 + c] * sv;
            hz += c_w[896 + (12 + g) * 12 + c] * sv;
            hn += c_w[896 + (24 + g) * 12 + c] * sv;
        }
        float rg = sigf(xr + hr);
        float zg = sigf(xz + hz);
        float ng = tanhff(xn + rg * hn);
        sn[g] = (1.f - zg) * ng + zg * s[g];
    }
#pragma unroll
    for (int c = 0; c < 12; ++c) g_s[(size_t)node * 12 + c] = sn[c];

    float un[8];
#pragma unroll
    for (int o = 0; o < 8; ++o) {
        float v = c_w[1496 + o];
#pragma unroll
        for (int c = 0; c < 12; ++c) v += c_w[1400 + o * 12 + c] * sn[c];
        un[o] = v;
    }
    {
        float4* op = (float4*)(uout + (size_t)node * 8);
        op[0] = make_float4(un[0], un[1], un[2], un[3]);
        op[1] = make_float4(un[4], un[5], un[6], un[7]);
    }

    if (last) {
        float hid[16];
#pragma unroll
        for (int t = 0; t < 16; ++t) {
            float h = c_w[1640 + t];
#pragma unroll
            for (int c = 0; c < 8; ++c) h += c_w[1512 + t * 8 + c] * un[c];
            hid[t] = fmaxf(h, 0.f);
        }
        float l0 = c_w[1688], l1 = c_w[1689];
#pragma unroll
        for (int t = 0; t < 16; ++t) {
            l0 += c_w[1656 + t] * hid[t];
            l1 += c_w[1656 + 16 + t] * hid[t];
        }
        float mx = fmaxf(l0, l1);
        float e0 = __expf(l0 - mx), e1 = __expf(l1 - mx);
        float inv = __fdividef(1.f, e0 + e1);
        float p0 = e0 * inv, p1 = e1 * inv;
        const float q0 = -0.70710678118654752440f, q1 = 0.70710678118654752440f;
        float xh = p0 * q0 + p1 * q1;
        float nu = p0 * (q0 - xh) * (q0 - xh) + p1 * (q1 - xh) * (q1 - xh);
        nu = fmaxf(nu, 1e-10f);
        out[node]         = xh;
        out[NNODE + node] = nu;
    }
}

extern "C" void kernel_launch(void* const* d_in, const int* in_sizes, int n_in,
                              void* d_out, int out_size) {
    const float* y    = (const float*)d_in[0];
    const float* H    = (const float*)d_in[1];
    const float* r    = (const float*)d_in[2];
    const float* nur  = (const float*)d_in[3];
    const float* adj  = (const float*)d_in[4];
    const float* W1w  = (const float*)d_in[5];
    const float* W1b  = (const float*)d_in[6];
    const float* b1   = (const float*)d_in[7];
    const float* Wm1  = (const float*)d_in[8];
    const float* Wm1b = (const float*)d_in[9];
    const float* Wm2  = (const float*)d_in[10];
    const float* Wm2b = (const float*)d_in[11];
    const float* wih  = (const float*)d_in[12];
    const float* whh  = (const float*)d_in[13];
    const float* bih  = (const float*)d_in[14];
    const float* bhh  = (const float*)d_in[15];
    const float* W2   = (const float*)d_in[16];
    const float* W2b  = (const float*)d_in[17];
    const float* b2   = (const float*)d_in[18];
    const float* Wr1  = (const float*)d_in[19];
    const float* Wr1b = (const float*)d_in[20];
    const float* Wr2  = (const float*)d_in[21];
    const float* Wr2b = (const float*)d_in[22];
    float* out = (float*)d_out;

    const int GEMM_SMEM = 2 * STAGEB;   // 110592 B
    cudaFuncSetAttribute(k_gemm, cudaFuncAttributeMaxDynamicSharedMemorySize, GEMM_SMEM);

    // fork: k_convcol (H pass) on side stream, k_csr (adj pass) on main stream
    cudaStream_t s2;
    cudaStreamCreateWithFlags(&s2, cudaStreamNonBlocking);
    cudaEvent_t evF, evJ;
    cudaEventCreateWithFlags(&evF, cudaEventDisableTiming);
    cudaEventCreateWithFlags(&evJ, cudaEventDisableTiming);
    cudaEventRecord(evF, 0);
    cudaStreamWaitEvent(s2, evF, 0);
    k_convcol<<<dim3(NB, NN / 128, 8), 128, 0, s2>>>(H, y);
    k_csr<<<NNODE / 8, 256>>>(adj, Wm1, Wm1b, Wm2, Wm2b, wih, whh, bih, bhh,
                              W2, W2b, b2, Wr1, Wr1b, Wr2, Wr2b);
    // load packed weights into constant bank (DtoD async copy, graph-legal)
    void* wsrc = nullptr;
    cudaGetSymbolAddress(&wsrc, g_wpack);
    cudaMemcpyToSymbolAsync(c_w, wsrc, NWELT * sizeof(float), 0,
                            cudaMemcpyDeviceToDevice, 0);
    cudaEventRecord(evJ, s2);
    cudaStreamWaitEvent(0, evJ, 0);

    k_gemm<<<dim3(8, 8, NB), 256, GEMM_SMEM>>>(H, W1w, W1b, b1);
    k_node<<<NNODE / 32, 128>>>(r, nur, 0, 0, out);
    k_node<<<NNODE / 32, 128>>>(r, nur, 1, 1, out);

    cudaEventDestroy(evF);
    cudaEventDestroy(evJ);
    cudaStreamDestroy(s2);
}